// round 13
// baseline (speedup 1.0000x reference)
#include <cuda_runtime.h>
#include <cuda_bf16.h>

// GaussianBlur: separable depthwise Gaussian (sigma=2), reflect_101,
// 32x3x512x512 fp32.  out = blur(x) + 254/255  (affine folded through blur).
//
// R12 -> R13: occupancy is register-file-bound, not smem-bound
// (48 regs x 320 thr = 15360/CTA -> only 4 CTAs fit the 64K-reg file;
//  smem 36.9KB x 5 = 184KB fits Blackwell's 227KB carveout).
// Single change: rolling window W 19 -> 15 (lookahead D 6 -> 2) +
// __launch_bounds__(320, 5) to pin regs <= 40 -> 5 CTAs/SM, 50 warps.
// Trade per-warp load lookahead for +25% warp-level latency hiding, which
// every previous round showed is this kernel's governing resource.

#define RAD   6
#define KS    13
#define IMGN  512
#define TW    128
#define TH    64
#define SW    (TW + 2 * RAD)        // 140
#define SWP   144                   // padded row stride (floats), %4==0
#define NTHR  320
#define VT    32                    // vertical outputs per task
#define VROWS (VT + 2 * RAD)        // 44 rows per strip
#define W     15                    // rolling window slots (13 taps + D=2)
#define PRE   14                    // prologue loads (W-1)
#define VTASKS (SW * (TH / VT))     // 280
#define HT    4                     // horizontal outputs per task (one float4)
#define HTASKS ((TW / HT) * TH)     // 2048

// 13-tap renormalized Gaussian (sigma=2): exp(-t^2/8)/S, t=-6..6,
// S = 5.00812248. Compile-time -> FFMA-imm under full unroll.
__device__ __forceinline__ constexpr float kg(int j) {
    constexpr float K[KS] = {
        2.2181965e-03f, 8.7731373e-03f, 2.7023174e-02f, 6.4825160e-02f,
        1.2110944e-01f, 1.7621313e-01f,
        1.9967563e-01f,
        1.7621313e-01f, 1.2110944e-01f, 6.4825160e-02f, 2.7023174e-02f,
        8.7731373e-03f, 2.2181965e-03f
    };
    return K[j];
}

__device__ __forceinline__ int mirror(int v) {
    // reflect_101, valid for |overhang| <= RAD
    const int a = ::abs(v);
    return ::min(a, 2 * (IMGN - 1) - a);
}

__global__ __launch_bounds__(NTHR, 5)
void gaussian_blur_fused(const float* __restrict__ in, float* __restrict__ out) {
    __shared__ __align__(16) float s_mid[TH * SWP];   // 64*144*4 = 36864 B

    const int x0 = blockIdx.x * TW;
    const int y0 = blockIdx.y * TH;
    const float* __restrict__ img  = in  + (size_t)blockIdx.z * (IMGN * IMGN);
    float*       __restrict__ oimg = out + (size_t)blockIdx.z * (IMGN * IMGN);
    const int tid = threadIdx.x;

    // ---- vertical pass: 280 tasks, one per thread ----
    // task: one x column, VT outputs, rolling W-reg window, D=2 lookahead.
    if (tid < VTASKS) {
        int x = tid, strip = 0;
        if (x >= SW) { x -= SW; strip = 1; }
        const int yy = y0 + strip * VT - RAD;

        const int  gx   = mirror(x0 + x - RAD);     // task-constant
        const bool y_ok = (yy >= 0) && (yy + VROWS <= IMGN);

        float w[W];
        if (y_ok) {
            const float* __restrict__ p = img + (size_t)yy * IMGN + gx;
            #pragma unroll
            for (int r = 0; r < PRE; ++r)
                w[r] = p[r * IMGN];                  // batched prologue, MLP=14
            #pragma unroll
            for (int i = 0; i < VT; ++i) {
                if (i + PRE < VROWS)                 // compile-time per iter
                    w[(i + PRE) % W] = p[(i + PRE) * IMGN];
                float acc = 0.0f;
                #pragma unroll
                for (int j = 0; j < KS; ++j)
                    acc = fmaf(w[(i + j) % W], kg(j), acc);
                s_mid[(strip * VT + i) * SWP + x] = acc;
            }
        } else {
            #pragma unroll
            for (int r = 0; r < PRE; ++r)
                w[r] = img[(size_t)mirror(yy + r) * IMGN + gx];
            #pragma unroll
            for (int i = 0; i < VT; ++i) {
                if (i + PRE < VROWS)
                    w[(i + PRE) % W] =
                        img[(size_t)mirror(yy + i + PRE) * IMGN + gx];
                float acc = 0.0f;
                #pragma unroll
                for (int j = 0; j < KS; ++j)
                    acc = fmaf(w[(i + j) % W], kg(j), acc);
                s_mid[(strip * VT + i) * SWP + x] = acc;
            }
        }
    }
    __syncthreads();

    // ---- horizontal pass: s_mid -> registers -> global (coalesced) ----
    // task: 4 consecutive x outputs of one row; 16-float window = exactly
    // 4 aligned LDS.128. Warp lanes -> consecutive x-segments: coalesced
    // LDS.128 and STG.128.
    const float OFS = 254.0f / 255.0f;
    for (int t = tid; t < HTASKS; t += NTHR) {
        const int row = t >> 5;          // TW/HT == 32
        const int xs  = t & 31;

        const float4* __restrict__ src =
            (const float4*)(s_mid + row * SWP) + xs;
        const float4 v0 = src[0], v1 = src[1], v2 = src[2], v3 = src[3];
        const float m[HT + KS - 1] = {
            v0.x, v0.y, v0.z, v0.w,  v1.x, v1.y, v1.z, v1.w,
            v2.x, v2.y, v2.z, v2.w,  v3.x, v3.y, v3.z, v3.w
        };

        float o[HT];
        #pragma unroll
        for (int i = 0; i < HT; ++i) {
            float acc = OFS;             // fold affine offset
            #pragma unroll
            for (int j = 0; j < KS; ++j)
                acc = fmaf(m[i + j], kg(j), acc);
            o[i] = acc;
        }

        *(float4*)(oimg + (size_t)(y0 + row) * IMGN + x0 + xs * HT) =
            make_float4(o[0], o[1], o[2], o[3]);
    }
}

extern "C" void kernel_launch(void* const* d_in, const int* in_sizes, int n_in,
                              void* d_out, int out_size) {
    const float* in = (const float*)d_in[0];
    float* out = (float*)d_out;
    const int n_imgs = in_sizes[0] / (IMGN * IMGN);   // 96
    dim3 grid(IMGN / TW, IMGN / TH, n_imgs);          // (4, 8, 96)
    gaussian_blur_fused<<<grid, NTHR>>>(in, out);
}

// round 15
// speedup vs baseline: 1.1789x; 1.1789x over previous
#include <cuda_runtime.h>
#include <cuda_bf16.h>

// GaussianBlur: separable depthwise Gaussian (sigma=2), reflect_101,
// 32x3x512x512 fp32.  out = blur(x) + 254/255  (affine folded through blur).
//
// R13 -> R14: R13's occupancy bid failed (regs crushed 48->32, issue 71->58%):
// the governing quantity is warps x per-warp-MLP, maximized at R12's point
// (48 regs / 4 CTAs / W=19). This round keeps R12's vertical pass verbatim
// and software-pipelines the HORIZONTAL pass: double-buffered quad prefetch,
// unrolled x2 (register-renamed buffers, no swap MOVs), so each iteration's
// 4x LDS.128 (29+ cyc) overlaps the previous iteration's 52 FFMAs.

#define RAD   6
#define KS    13
#define IMGN  512
#define TW    128
#define TH    64
#define SW    (TW + 2 * RAD)        // 140
#define SWP   144                   // padded row stride (floats), %4==0
#define NTHR  320
#define VT    32                    // vertical outputs per task
#define VROWS (VT + 2 * RAD)        // 44 rows per strip
#define W     19                    // rolling window slots (13 taps + D=6)
#define PRE   18                    // prologue loads (W-1)
#define VTASKS (SW * (TH / VT))     // 280
#define HT    4                     // horizontal outputs per task (one float4)
#define HTASKS ((TW / HT) * TH)     // 2048

// 13-tap renormalized Gaussian (sigma=2): exp(-t^2/8)/S, t=-6..6,
// S = 5.00812248. Compile-time -> FFMA-imm under full unroll.
__device__ __forceinline__ constexpr float kg(int j) {
    constexpr float K[KS] = {
        2.2181965e-03f, 8.7731373e-03f, 2.7023174e-02f, 6.4825160e-02f,
        1.2110944e-01f, 1.7621313e-01f,
        1.9967563e-01f,
        1.7621313e-01f, 1.2110944e-01f, 6.4825160e-02f, 2.7023174e-02f,
        8.7731373e-03f, 2.2181965e-03f
    };
    return K[j];
}

__device__ __forceinline__ int mirror(int v) {
    // reflect_101, valid for |overhang| <= RAD
    const int a = ::abs(v);
    return ::min(a, 2 * (IMGN - 1) - a);
}

// load the 4 quads (16-float window) for horizontal task t
__device__ __forceinline__ void hload(float4 q[4], const float* s_mid, int t) {
    const int row = t >> 5;              // TW/HT == 32
    const int xs  = t & 31;
    const float4* __restrict__ src = (const float4*)(s_mid + row * SWP) + xs;
    q[0] = src[0]; q[1] = src[1]; q[2] = src[2]; q[3] = src[3];
}

// 13-tap conv over the 16-float window; coalesced STG.128
__device__ __forceinline__ void hcompute(const float4 q[4], float* oimg,
                                         int x0, int y0, int t) {
    const float m[HT + KS - 1] = {
        q[0].x, q[0].y, q[0].z, q[0].w,  q[1].x, q[1].y, q[1].z, q[1].w,
        q[2].x, q[2].y, q[2].z, q[2].w,  q[3].x, q[3].y, q[3].z, q[3].w
    };
    const float OFS = 254.0f / 255.0f;
    float o[HT];
    #pragma unroll
    for (int i = 0; i < HT; ++i) {
        float acc = OFS;                 // fold affine offset
        #pragma unroll
        for (int j = 0; j < KS; ++j)
            acc = fmaf(m[i + j], kg(j), acc);
        o[i] = acc;
    }
    const int row = t >> 5;
    const int xs  = t & 31;
    *(float4*)(oimg + (size_t)(y0 + row) * IMGN + x0 + xs * HT) =
        make_float4(o[0], o[1], o[2], o[3]);
}

__global__ __launch_bounds__(NTHR, 4)
void gaussian_blur_fused(const float* __restrict__ in, float* __restrict__ out) {
    __shared__ __align__(16) float s_mid[TH * SWP];   // 64*144*4 = 36864 B

    const int x0 = blockIdx.x * TW;
    const int y0 = blockIdx.y * TH;
    const float* __restrict__ img  = in  + (size_t)blockIdx.z * (IMGN * IMGN);
    float*       __restrict__ oimg = out + (size_t)blockIdx.z * (IMGN * IMGN);
    const int tid = threadIdx.x;

    // ---- vertical pass (R12 verbatim): rolling W-reg window, D=6 lookahead ----
    if (tid < VTASKS) {
        int x = tid, strip = 0;
        if (x >= SW) { x -= SW; strip = 1; }
        const int yy = y0 + strip * VT - RAD;

        const int  gx   = mirror(x0 + x - RAD);     // task-constant
        const bool y_ok = (yy >= 0) && (yy + VROWS <= IMGN);

        float w[W];
        if (y_ok) {
            const float* __restrict__ p = img + (size_t)yy * IMGN + gx;
            #pragma unroll
            for (int r = 0; r < PRE; ++r)
                w[r] = p[r * IMGN];                  // batched prologue, MLP=18
            #pragma unroll
            for (int i = 0; i < VT; ++i) {
                if (i + PRE < VROWS)                 // compile-time per iter
                    w[(i + PRE) % W] = p[(i + PRE) * IMGN];
                float acc = 0.0f;
                #pragma unroll
                for (int j = 0; j < KS; ++j)
                    acc = fmaf(w[(i + j) % W], kg(j), acc);
                s_mid[(strip * VT + i) * SWP + x] = acc;
            }
        } else {
            #pragma unroll
            for (int r = 0; r < PRE; ++r)
                w[r] = img[(size_t)mirror(yy + r) * IMGN + gx];
            #pragma unroll
            for (int i = 0; i < VT; ++i) {
                if (i + PRE < VROWS)
                    w[(i + PRE) % W] =
                        img[(size_t)mirror(yy + i + PRE) * IMGN + gx];
                float acc = 0.0f;
                #pragma unroll
                for (int j = 0; j < KS; ++j)
                    acc = fmaf(w[(i + j) % W], kg(j), acc);
                s_mid[(strip * VT + i) * SWP + x] = acc;
            }
        }
    }
    __syncthreads();

    // ---- horizontal pass: double-buffered software pipeline, unrolled x2 ----
    {
        float4 qa[4], qb[4];
        int t = tid;
        hload(qa, s_mid, t);                         // prime buffer A
        while (t < HTASKS) {
            const int t1 = t + NTHR;
            if (t1 < HTASKS) hload(qb, s_mid, t1);   // prefetch B
            hcompute(qa, oimg, x0, y0, t);           // compute A (hides B's LDS)
            if (t1 < HTASKS) {
                const int t2 = t1 + NTHR;
                if (t2 < HTASKS) hload(qa, s_mid, t2);   // prefetch A
                hcompute(qb, oimg, x0, y0, t1);          // compute B
                t = t2;
            } else {
                t = t1;
            }
        }
    }
}

extern "C" void kernel_launch(void* const* d_in, const int* in_sizes, int n_in,
                              void* d_out, int out_size) {
    const float* in = (const float*)d_in[0];
    float* out = (float*)d_out;
    const int n_imgs = in_sizes[0] / (IMGN * IMGN);   // 96
    dim3 grid(IMGN / TW, IMGN / TH, n_imgs);          // (4, 8, 96)
    gaussian_blur_fused<<<grid, NTHR>>>(in, out);
}